// round 6
// baseline (speedup 1.0000x reference)
#include <cuda_runtime.h>
#include <math.h>
#include <stdint.h>

#define BATCH  32
#define TLEN   2048
#define HE     1024
#define CHUNKS 32
#define ROWS_PER_CTA (TLEN / CHUNKS)   // 64
#define SROWS  4                        // rows per pipeline stage (16KB)
#define NBUF   2                        // double buffer, prefetch distance 1
#define NST    (ROWS_PER_CTA / SROWS)   // 16 stages
#define THREADS 256
#define TILE_FLOATS (SROWS * HE)        // 4096 floats = 16KB
// dynamic smem: [we: 1024][buf: 2 x 4096] = 36KB -> 6 CTAs/SM
#define DSMEM_FLOATS (HE + NBUF * TILE_FLOATS)

// Cross-CTA partials (allocation-free scratch)
__device__ float g_pz[BATCH * CHUNKS];
__device__ float g_pacc[BATCH * CHUNKS * HE];
__device__ unsigned int g_ticket[BATCH];   // zero-init; self-resetting

__device__ __forceinline__ void cp_async16(uint32_t saddr, const void* gaddr) {
    asm volatile("cp.async.cg.shared.global [%0], [%1], 16;\n" :: "r"(saddr), "l"(gaddr));
}
__device__ __forceinline__ void cp_commit() {
    asm volatile("cp.async.commit_group;\n" ::: "memory");
}
template<int N>
__device__ __forceinline__ void cp_wait() {
    asm volatile("cp.async.wait_group %0;\n" :: "n"(N) : "memory");
}

__global__ __launch_bounds__(THREADS, 6)
void attn_fused_kernel(const float* __restrict__ hidden,   // (2,32,1024)
                       const float* __restrict__ enc,      // (32,2048,1024)
                       const float* __restrict__ mask,     // (32,2048)
                       const float* __restrict__ attn_w,   // (3072,)
                       const float* __restrict__ attn_b,   // (1,)
                       float* __restrict__ out)            // (32,1024)
{
    extern __shared__ float dsm[];
    float* s_we  = dsm;                 // 1024
    float* s_buf = dsm + HE;            // NBUF x 4096

    __shared__ float s_wr[SROWS];
    __shared__ float s_mask[ROWS_PER_CTA];
    __shared__ float s_red[THREADS / 32];
    __shared__ float s_hb;
    __shared__ unsigned s_ticket;

    const int tid   = threadIdx.x;
    const int b     = blockIdx.y;
    const int chunk = blockIdx.x;
    const int lane  = tid & 31;
    const int warp  = tid >> 5;
    const int t0    = chunk * ROWS_PER_CTA;

    const uint32_t smem_base = (uint32_t)__cvta_generic_to_shared(s_buf);
    const float* gtile0 = enc + ((size_t)b * TLEN + t0) * HE;

    // ---- prefetch stage 0 immediately (overlaps prologue) ----
    {
        const char* g = (const char*)gtile0;
        #pragma unroll
        for (int k = 0; k < TILE_FLOATS / 4 / THREADS; k++) {
            int idx = tid + k * THREADS;
            cp_async16(smem_base + idx * 16, g + (size_t)idx * 16);
        }
        cp_commit();
    }

    // ---- prologue: w_e, mask chunk, hb ----
    for (int i = tid; i < HE; i += THREADS) s_we[i] = attn_w[2048 + i];
    if (tid < ROWS_PER_CTA) s_mask[tid] = mask[(size_t)b * TLEN + t0 + tid];

    float hsum = 0.f;
    for (int i = tid; i < 2048; i += THREADS) {
        int j = i >> 10, k = i & 1023;
        hsum += hidden[(size_t)j * BATCH * HE + (size_t)b * HE + k] * attn_w[i];
    }
    #pragma unroll
    for (int o = 16; o; o >>= 1) hsum += __shfl_xor_sync(0xffffffffu, hsum, o);
    if (lane == 0) s_red[warp] = hsum;
    __syncthreads();
    if (tid == 0) {
        float s = 0.f;
        #pragma unroll
        for (int w = 0; w < THREADS / 32; w++) s += s_red[w];
        s_hb = s + attn_b[0];
    }
    __syncthreads();
    const float hb = s_hb;

    float  z = 0.f;
    float4 acc = make_float4(0.f, 0.f, 0.f, 0.f);
    const float4* we4 = (const float4*)s_we;

    for (int s = 0; s < NST; s++) {
        // issue prefetch for stage s+1 into the other buffer, then wait for s
        if (s + 1 < NST) {
            const char* g = (const char*)(gtile0 + (size_t)(s + 1) * TILE_FLOATS);
            uint32_t sb = smem_base + ((s + 1) & 1) * (TILE_FLOATS * 4);
            #pragma unroll
            for (int k = 0; k < TILE_FLOATS / 4 / THREADS; k++) {
                int idx = tid + k * THREADS;
                cp_async16(sb + idx * 16, g + (size_t)idx * 16);
            }
            cp_commit();
            cp_wait<1>();      // stage s complete, s+1 in flight
        } else {
            cp_wait<0>();
        }
        __syncthreads();

        const float* buf = s_buf + (s & 1) * TILE_FLOATS;

        // ---- energy: warps 0..3 each compute one row; lane0 does the exp ----
        if (warp < SROWS) {
            const float4* row4 = (const float4*)(buf + warp * HE);
            float e = 0.f;
            #pragma unroll
            for (int i = 0; i < 8; i++) {
                float4 v = row4[lane + 32 * i];
                float4 w = we4[lane + 32 * i];
                e += v.x * w.x + v.y * w.y + v.z * w.z + v.w * w.w;
            }
            #pragma unroll
            for (int o = 16; o; o >>= 1) e += __shfl_xor_sync(0xffffffffu, e, o);
            if (lane == 0) {
                float mk = s_mask[s * SROWS + warp];
                // energies*mask before softmax; exp (no max: |e|~O(6)); *mask after
                s_wr[warp] = __expf((e + hb) * mk) * mk;
            }
        }
        __syncthreads();

        // ---- weights (broadcast LDS) + accumulate: thread owns 4 cols ----
        float wr[SROWS];
        #pragma unroll
        for (int r = 0; r < SROWS; r++) { wr[r] = s_wr[r]; z += wr[r]; }

        const float4* bufv = (const float4*)buf;
        #pragma unroll
        for (int r = 0; r < SROWS; r++) {
            float4 v = bufv[r * (HE / 4) + tid];
            acc.x += wr[r] * v.x; acc.y += wr[r] * v.y;
            acc.z += wr[r] * v.z; acc.w += wr[r] * v.w;
        }
        __syncthreads();   // buffer (s&1) gets refilled at iteration s+1
    }

    // ---- write partials ----
    const int pidx = b * CHUNKS + chunk;
    if (tid == 0) g_pz[pidx] = z;
    ((float4*)(g_pacc + (size_t)pidx * HE))[tid] = acc;
    __threadfence();
    __syncthreads();
    if (tid == 0) s_ticket = atomicAdd(&g_ticket[b], 1u);
    __syncthreads();

    // ---- last CTA of this batch combines ----
    if (s_ticket == CHUNKS - 1) {
        __threadfence();   // acquire peer partials

        float Z = 0.f;
        #pragma unroll
        for (int c = 0; c < CHUNKS; c++) Z += g_pz[b * CHUNKS + c];
        const float inv = 1.f / Z;

        float4 o = make_float4(0.f, 0.f, 0.f, 0.f);
        #pragma unroll
        for (int c = 0; c < CHUNKS; c++) {
            float4 a = ((const float4*)(g_pacc + (size_t)(b * CHUNKS + c) * HE))[tid];
            o.x += a.x; o.y += a.y; o.z += a.z; o.w += a.w;
        }
        o.x *= inv; o.y *= inv; o.z *= inv; o.w *= inv;
        ((float4*)(out + (size_t)b * HE))[tid] = o;

        if (tid == 0) g_ticket[b] = 0;   // self-reset for next replay
    }
}

extern "C" void kernel_launch(void* const* d_in, const int* in_sizes, int n_in,
                              void* d_out, int out_size)
{
    const float* hidden = (const float*)d_in[0];  // (2,32,1024)
    const float* enc    = (const float*)d_in[1];  // (32,2048,1024)
    const float* mask   = (const float*)d_in[2];  // (32,2048)
    const float* attn_w = (const float*)d_in[3];  // (3072,)
    const float* attn_b = (const float*)d_in[4];  // (1,)
    float* out = (float*)d_out;                   // (32,1024)

    static bool attr_set = false;
    if (!attr_set) {
        cudaFuncSetAttribute(attn_fused_kernel,
                             cudaFuncAttributeMaxDynamicSharedMemorySize,
                             DSMEM_FLOATS * sizeof(float));
        attr_set = true;
    }

    dim3 grid(CHUNKS, BATCH);
    attn_fused_kernel<<<grid, THREADS, DSMEM_FLOATS * sizeof(float)>>>(
        hidden, enc, mask, attn_w, attn_b, out);
}

// round 8
// speedup vs baseline: 1.4752x; 1.4752x over previous
#include <cuda_runtime.h>
#include <math.h>
#include <stdint.h>

#define BATCH   32
#define TLEN    2048
#define HE      1024
#define NCHUNK  9                 // 288 CTAs = one full wave at occ 2 (148 SMs)
#define CBASE   (TLEN / NCHUNK)   // 227
#define CREM    (TLEN - CBASE * NCHUNK) // 5 chunks get one extra row
#define THREADS 256
#define WARPS   (THREADS / 32)

// Cross-CTA partials (allocation-free scratch)
__device__ float g_pz[BATCH * NCHUNK];
__device__ float g_pacc[BATCH * NCHUNK * HE];
__device__ unsigned int g_ticket[BATCH];   // zero-init; self-resetting

__global__ __launch_bounds__(THREADS, 2)
void attn_fused_kernel(const float* __restrict__ hidden,   // (2,32,1024)
                       const float* __restrict__ enc,      // (32,2048,1024)
                       const float* __restrict__ mask,     // (32,2048)
                       const float* __restrict__ attn_w,   // (3072,)
                       const float* __restrict__ attn_b,   // (1,)
                       float* __restrict__ out)            // (32,1024)
{
    __shared__ float s_acc[WARPS * HE];    // 32KB warp-partial reduce
    __shared__ float s_z[WARPS];
    __shared__ float s_red[WARPS];
    __shared__ float s_hb;
    __shared__ unsigned s_ticket;

    const int tid   = threadIdx.x;
    const int lane  = tid & 31;
    const int warp  = tid >> 5;
    const int b     = blockIdx.x / NCHUNK;
    const int chunk = blockIdx.x % NCHUNK;

    const int t_begin = chunk * CBASE + min(chunk, CREM);
    const int t_end   = t_begin + CBASE + (chunk < CREM ? 1 : 0);

    // ---- w_e register-resident: lane l holds float4 slots l+32i ----
    const float4* w4g = (const float4*)attn_w;   // attn_w[2048..3071] -> float4[512..767]
    float4 we[8];
    #pragma unroll
    for (int i = 0; i < 8; i++) we[i] = __ldg(&w4g[512 + lane + 32 * i]);

    // ---- hb = hid_flat[b].w_h + bias ----
    float hsum = 0.f;
    for (int i = tid; i < 2048; i += THREADS) {
        int j = i >> 10, k = i & 1023;
        hsum += hidden[(size_t)j * BATCH * HE + (size_t)b * HE + k] * attn_w[i];
    }
    #pragma unroll
    for (int o = 16; o; o >>= 1) hsum += __shfl_xor_sync(0xffffffffu, hsum, o);
    if (lane == 0) s_red[warp] = hsum;
    __syncthreads();
    if (tid == 0) {
        float s = 0.f;
        #pragma unroll
        for (int w = 0; w < WARPS; w++) s += s_red[w];
        s_hb = s + attn_b[0];
    }
    __syncthreads();
    const float hb = s_hb;

    // ---- mainloop: warp owns rows t_begin+warp, +8, ... ; no barriers ----
    const float*  mrow = mask + (size_t)b * TLEN;
    float z = 0.f;
    float4 acc[8];
    #pragma unroll
    for (int i = 0; i < 8; i++) acc[i] = make_float4(0.f, 0.f, 0.f, 0.f);

    for (int t = t_begin + warp; t < t_end; t += WARPS) {
        const float4* row4 = (const float4*)(enc + ((size_t)b * TLEN + t) * HE);
        float4 v[8];
        #pragma unroll
        for (int i = 0; i < 8; i++) v[i] = row4[lane + 32 * i];   // 8 LDG.128 in flight

        float e = 0.f;
        #pragma unroll
        for (int i = 0; i < 8; i++)
            e += v[i].x * we[i].x + v[i].y * we[i].y + v[i].z * we[i].z + v[i].w * we[i].w;
        #pragma unroll
        for (int o = 16; o; o >>= 1) e += __shfl_xor_sync(0xffffffffu, e, o);

        const float mk = mrow[t];
        // energies*mask before softmax; exp without max (|e|~O(6)); *mask after
        const float w = __expf((e + hb) * mk) * mk;
        z += w;
        #pragma unroll
        for (int i = 0; i < 8; i++) {
            acc[i].x += w * v[i].x; acc[i].y += w * v[i].y;
            acc[i].z += w * v[i].z; acc[i].w += w * v[i].w;
        }
    }

    // ---- CTA reduction of 8 warp partials ----
    #pragma unroll
    for (int i = 0; i < 8; i++)
        ((float4*)s_acc)[warp * (HE / 4) + i * 32 + lane] = acc[i];
    if (lane == 0) s_z[warp] = z;
    __syncthreads();

    float4 o = make_float4(0.f, 0.f, 0.f, 0.f);
    #pragma unroll
    for (int w = 0; w < WARPS; w++) {
        float4 a = ((const float4*)s_acc)[w * (HE / 4) + tid];
        o.x += a.x; o.y += a.y; o.z += a.z; o.w += a.w;
    }
    float zc = 0.f;
    if (tid == 0) {
        #pragma unroll
        for (int w = 0; w < WARPS; w++) zc += s_z[w];
    }

    // ---- write partials; ticketed last-CTA combine per batch ----
    const int pidx = b * NCHUNK + chunk;
    if (tid == 0) g_pz[pidx] = zc;
    ((float4*)(g_pacc + (size_t)pidx * HE))[tid] = o;
    __threadfence();
    __syncthreads();
    if (tid == 0) s_ticket = atomicAdd(&g_ticket[b], 1u);
    __syncthreads();

    if (s_ticket == NCHUNK - 1) {
        __threadfence();   // acquire peer partials

        float Z = 0.f;
        #pragma unroll
        for (int c = 0; c < NCHUNK; c++) Z += g_pz[b * NCHUNK + c];
        const float inv = 1.f / Z;

        float4 r = make_float4(0.f, 0.f, 0.f, 0.f);
        #pragma unroll
        for (int c = 0; c < NCHUNK; c++) {
            float4 a = ((const float4*)(g_pacc + (size_t)(b * NCHUNK + c) * HE))[tid];
            r.x += a.x; r.y += a.y; r.z += a.z; r.w += a.w;
        }
        r.x *= inv; r.y *= inv; r.z *= inv; r.w *= inv;
        ((float4*)(out + (size_t)b * HE))[tid] = r;

        if (tid == 0) g_ticket[b] = 0;   // self-reset for next graph replay
    }
}

extern "C" void kernel_launch(void* const* d_in, const int* in_sizes, int n_in,
                              void* d_out, int out_size)
{
    const float* hidden = (const float*)d_in[0];  // (2,32,1024)
    const float* enc    = (const float*)d_in[1];  // (32,2048,1024)
    const float* mask   = (const float*)d_in[2];  // (32,2048)
    const float* attn_w = (const float*)d_in[3];  // (3072,)
    const float* attn_b = (const float*)d_in[4];  // (1,)
    float* out = (float*)d_out;                   // (32,1024)

    attn_fused_kernel<<<BATCH * NCHUNK, THREADS>>>(
        hidden, enc, mask, attn_w, attn_b, out);
}